// round 4
// baseline (speedup 1.0000x reference)
#include <cuda_runtime.h>
#include <math.h>

#define KTOT  2304          // 9*256, k = (ky*3+kx)*256 + c
#define NANCH 76725
#define MAXDET 300

#define BM 128
#define BN 128
#define BK 16
#define NT  144             // KTOT/BK
#define BUFSZ (8525*256)

// ---------------- scratch (device globals; no allocation) ----------------
__device__ float  g_feat[BUFSZ];
__device__ float  g_hA0[BUFSZ];
__device__ float  g_hA1[BUFSZ];
__device__ float  g_hB0[BUFSZ];
__device__ float  g_hB1[BUFSZ];
__device__ float  g_wc[4 * 256 * KTOT];   // cls hidden weights, k-major
__device__ float  g_wr[4 * 256 * KTOT];   // reg hidden weights, k-major
__device__ float  g_wo[45 * KTOT];        // cls_ow (9 rows) + reg_ow (36 rows)
__device__ float  g_scores[NANCH];
__device__ float4 g_boxes[NANCH];
__device__ float  g_cs[NANCH];
__device__ float4 g_cb[NANCH];
__device__ float  g_carea[NANCH];

// per-level tables
__constant__ int c_H[5]   = {80, 40, 20, 10, 5};
__constant__ int c_Pb[5]  = {0, 1638400, 2048000, 2150400, 2176000}; // pixel_off*256
__constant__ int c_str[5] = {8, 16, 32, 64, 128};
__constant__ int c_ao[5]  = {0, 57600, 72000, 75600, 76500};

// ---------------- weight transpose: OIHW row (c*9 + rs) -> k-major (rs*256 + c) ----
// rows: [0,1024) cls hidden, [1024,2048) reg hidden, [2048,2057) cls_ow, [2057,2093) reg_ow
__global__ void transpose_w(const float* __restrict__ cw, const float* __restrict__ rw,
                            const float* __restrict__ cow, const float* __restrict__ row_)
{
    const int r = blockIdx.x;
    const float* src;
    float* dst;
    if (r < 1024)       { src = cw  + (size_t)r * KTOT;          dst = g_wc + (size_t)r * KTOT; }
    else if (r < 2048)  { src = rw  + (size_t)(r - 1024) * KTOT; dst = g_wr + (size_t)(r - 1024) * KTOT; }
    else if (r < 2057)  { src = cow + (size_t)(r - 2048) * KTOT; dst = g_wo + (size_t)(r - 2048) * KTOT; }
    else                { src = row_ + (size_t)(r - 2057) * KTOT; dst = g_wo + (size_t)(r - 2048) * KTOT; }
    for (int k = threadIdx.x; k < KTOT; k += 256) {
        int rs = k >> 8, c = k & 255;
        dst[k] = src[c * 9 + rs];
    }
}

// ---------------- fused implicit-GEMM conv over all 5 levels x 2 heads ----------------
// Serial single-accumulator FMA chain, k ascending in (r, s, c) order with c fastest:
// reproduces the associativity chain of cutlass/cuDNN NHWC fprop implicit GEMM.
template <int OUTMODE>
__global__ __launch_bounds__(256, 2)
void conv_fused(const float* __restrict__ inC, const float* __restrict__ inR,
                const float* __restrict__ Wc,  const float* __restrict__ Wr,
                const float* __restrict__ bc,  const float* __restrict__ br,
                float* outC, float* outR)
{
    const int bx = blockIdx.x;
    int l, ts;
    if      (bx < 50) { l = 0; ts = 0;  }
    else if (bx < 63) { l = 1; ts = 50; }
    else if (bx < 67) { l = 2; ts = 63; }
    else if (bx < 68) { l = 3; ts = 67; }
    else              { l = 4; ts = 68; }
    const int H = c_H[l];
    const int P = H * H;
    const int base = c_Pb[l];
    const int n0 = (bx - ts) * BN;
    const int z  = blockIdx.z;

    const float* in   = (z ? inR : inC) + base;
    const float* Wt   =  z ? Wr : Wc;
    const float* bias =  z ? br : bc;
    const int    M    = OUTMODE ? (z ? 36 : 9) : 256;
    const int    m0   = blockIdx.y * BM;

    const int tid = threadIdx.x;
    const int tx = tid & 15, ty = tid >> 4;

    __shared__ float As[BK][BM];
    __shared__ float Bs[BK][BN];

    float acc[8][8];
#pragma unroll
    for (int i = 0; i < 8; i++)
#pragma unroll
        for (int j = 0; j < 8; j++) acc[i][j] = 0.f;

    // ---- B loader precompute ----
    const int lane16 = tid & 15;
    const int kr     = tid >> 4;       // c offset within chunk
    int py[8], px[8];
#pragma unroll
    for (int j = 0; j < 8; j++) {
        int p = n0 + lane16 + j * 16;
        if (p < P) { py[j] = p / H; px[j] = p - py[j] * H; }
        else       { py[j] = -100000; px[j] = -100000; }
    }

    // ---- A loader indices (weights pre-transposed to k-major, contiguous) ----
    const int  arow = tid >> 1;
    const int  aq   = (tid & 1) * 2;
    const bool aval = (m0 + arow) < M;
    const float* Arow = Wt + (size_t)(m0 + arow) * KTOT;

    for (int kt = 0; kt < NT; kt++) {
        const int k0 = kt * BK;
        float4 a0, a1;
        if (aval) {
            a0 = *(const float4*)(Arow + k0 + aq * 4);
            a1 = *(const float4*)(Arow + k0 + aq * 4 + 4);
        } else {
            a0 = make_float4(0.f, 0.f, 0.f, 0.f);
            a1 = a0;
        }
        As[aq * 4 + 0][arow] = a0.x;  As[aq * 4 + 1][arow] = a0.y;
        As[aq * 4 + 2][arow] = a0.z;  As[aq * 4 + 3][arow] = a0.w;
        As[aq * 4 + 4][arow] = a1.x;  As[aq * 4 + 5][arow] = a1.y;
        As[aq * 4 + 6][arow] = a1.z;  As[aq * 4 + 7][arow] = a1.w;

        // B tile: chunk kt -> rs = kt>>4 (fixed spatial tap), c = (kt&15)*16 + kr
        {
            const int rs = kt >> 4;
            const int c  = ((kt & 15) << 4) + kr;
            const int dy = (rs / 3) - 1, dx = (rs % 3) - 1;
            const float* cptr = in + (size_t)c * P;
#pragma unroll
            for (int j = 0; j < 8; j++) {
                int iy = py[j] + dy, ix = px[j] + dx;
                float v = 0.f;
                if (iy >= 0 && iy < H && ix >= 0 && ix < H)
                    v = __ldg(cptr + iy * H + ix);
                Bs[kr][lane16 + j * 16] = v;
            }
        }
        __syncthreads();

        // strict serial ascending FMA chain (matches library per-element sum)
#pragma unroll
        for (int kk = 0; kk < BK; kk++) {
            float a[8], b[8];
            *(float4*)&a[0] = *(const float4*)&As[kk][ty * 8];
            *(float4*)&a[4] = *(const float4*)&As[kk][ty * 8 + 4];
            *(float4*)&b[0] = *(const float4*)&Bs[kk][tx * 8];
            *(float4*)&b[4] = *(const float4*)&Bs[kk][tx * 8 + 4];
#pragma unroll
            for (int i = 0; i < 8; i++)
#pragma unroll
                for (int j = 0; j < 8; j++)
                    acc[i][j] = __fmaf_rn(a[i], b[j], acc[i][j]);
        }
        __syncthreads();
    }

    // ---------------- epilogues ----------------
    if (OUTMODE == 0) {
        float* out = (z ? outR : outC) + base;
#pragma unroll
        for (int i = 0; i < 8; i++) {
            const int m = m0 + ty * 8 + i;
            const float bsum = bias[m];
#pragma unroll
            for (int j = 0; j < 8; j++) {
                int p = n0 + tx * 8 + j;
                if (p < P) out[(size_t)m * P + p] = fmaxf(__fadd_rn(acc[i][j], bsum), 0.f);
            }
        }
    } else if (z == 0) {  // cls out: sigmoid via double (correctly-rounded estimate)
        const int aoff = c_ao[l];
#pragma unroll
        for (int i = 0; i < 8; i++) {
            const int m = m0 + ty * 8 + i;
            if (m < 9) {
                const float bsum = bias[m];
#pragma unroll
                for (int j = 0; j < 8; j++) {
                    int p = n0 + tx * 8 + j;
                    if (p < P) {
                        float logit = __fadd_rn(acc[i][j], bsum);
                        double s = 1.0 / (1.0 + exp(-(double)logit));
                        g_scores[aoff + p * 9 + m] = (float)s;
                    }
                }
            }
        }
    } else {  // reg out + anchor decode
        const int aoff = c_ao[l];
        const int stride = c_str[l];
#pragma unroll
        for (int i = 0; i < 8; i += 4) {
            const int m = m0 + ty * 8 + i;
            if (m + 3 < 36) {
                const int a = m >> 2;
                const int ri = a / 3, si = a - 3 * ri;
                const double ratio = (ri == 0) ? 0.5 : ((ri == 1) ? 1.0 : 2.0);
                const double scl   = (si == 0) ? 1.0 : exp2((double)si / 3.0);
                const double bsz   = (double)(stride * 4) * scl;
                const double wA    = sqrt((bsz * bsz) / ratio);
                const double hA    = wA * ratio;
                const float b0v = bias[m + 0], b1v = bias[m + 1];
                const float b2v = bias[m + 2], b3v = bias[m + 3];
#pragma unroll
                for (int j = 0; j < 8; j++) {
                    int p = n0 + tx * 8 + j;
                    if (p < P) {
                        int yy = p / H;
                        int xx = p - yy * H;
                        double cxd = ((double)xx + 0.5) * (double)stride;
                        double cyd = ((double)yy + 0.5) * (double)stride;
                        float ax1 = (float)(cxd - 0.5 * wA);
                        float ay1 = (float)(cyd - 0.5 * hA);
                        float ax2 = (float)(cxd + 0.5 * wA);
                        float ay2 = (float)(cyd + 0.5 * hA);
                        float aw = __fsub_rn(ax2, ax1), ah = __fsub_rn(ay2, ay1);
                        float acx = __fadd_rn(ax1, 0.5f * aw);
                        float acy = __fadd_rn(ay1, 0.5f * ah);
                        float t0 = __fadd_rn(acc[i + 0][j], b0v);
                        float t1 = __fadd_rn(acc[i + 1][j], b1v);
                        float t2 = __fadd_rn(acc[i + 2][j], b2v);
                        float t3 = __fadd_rn(acc[i + 3][j], b3v);
                        float pcx = __fadd_rn(acx, __fmul_rn(__fmul_rn(t0, 0.1f), aw));
                        float pcy = __fadd_rn(acy, __fmul_rn(__fmul_rn(t1, 0.1f), ah));
                        float pw  = __fmul_rn((float)exp((double)__fmul_rn(t2, 0.2f)), aw);
                        float ph  = __fmul_rn((float)exp((double)__fmul_rn(t3, 0.2f)), ah);
                        float x1 = __fsub_rn(pcx, 0.5f * pw), y1 = __fsub_rn(pcy, 0.5f * ph);
                        float x2 = __fadd_rn(pcx, 0.5f * pw), y2 = __fadd_rn(pcy, 0.5f * ph);
                        x1 = fminf(fmaxf(x1, 0.f), 640.f);
                        y1 = fminf(fmaxf(y1, 0.f), 640.f);
                        x2 = fminf(fmaxf(x2, 0.f), 640.f);
                        y2 = fminf(fmaxf(y2, 0.f), 640.f);
                        g_boxes[aoff + p * 9 + a] = make_float4(x1, y1, x2, y2);
                    }
                }
            }
        }
    }
}

// ---------------- single-block NMS (compaction + greedy loop) ----------------
__global__ __launch_bounds__(1024)
void nms_kernel(float* __restrict__ out)
{
    const int T = 1024;
    const int tid = threadIdx.x;

    __shared__ int    s_warpcnt[32];
    __shared__ int    s_woff[32];
    __shared__ int    s_base;
    __shared__ float  s_val[1024];
    __shared__ int    s_idx[1024];
    __shared__ float  s_selS[MAXDET];
    __shared__ float4 s_selB[MAXDET];
    __shared__ float  s_bj[5];

    if (tid == 0) s_base = 0;
    __syncthreads();

    // deterministic ordered compaction of candidates (score > 0.05)
    for (int c0 = 0; c0 < NANCH; c0 += T) {
        const int i = c0 + tid;
        float s = -1.f;
        bool pred = false;
        if (i < NANCH) {
            s = g_scores[i];
            pred = (s > 0.05f);
        }
        unsigned mask = __ballot_sync(0xffffffffu, pred);
        const int lane = tid & 31, w = tid >> 5;
        const int pos = __popc(mask & ((1u << lane) - 1u));
        if (lane == 0) s_warpcnt[w] = __popc(mask);
        __syncthreads();
        if (tid == 0) {
            int acc = s_base;
            for (int ww = 0; ww < 32; ww++) { s_woff[ww] = acc; acc += s_warpcnt[ww]; }
            s_base = acc;
        }
        __syncthreads();
        if (pred) {
            const int o = s_woff[w] + pos;
            g_cs[o] = s;
            float4 b = g_boxes[i];
            g_cb[o] = b;
            g_carea[o] = __fmul_rn(__fsub_rn(b.z, b.x), __fsub_rn(b.w, b.y));
        }
        __syncthreads();
    }
    const int ns = s_base;

    // greedy NMS: 300 x (argmax + suppress)
    int nsel = MAXDET;
    for (int it = 0; it < MAXDET; it++) {
        float bv = -INFINITY; int bi = 0x7fffffff;
        for (int idx = tid; idx < ns; idx += T) {
            float v = g_cs[idx];
            if (v > bv || (v == bv && idx < bi)) { bv = v; bi = idx; }
        }
        s_val[tid] = bv; s_idx[tid] = bi;
        __syncthreads();
        for (int off = T / 2; off > 0; off >>= 1) {
            if (tid < off) {
                float v2 = s_val[tid + off]; int i2 = s_idx[tid + off];
                if (v2 > s_val[tid] || (v2 == s_val[tid] && i2 < s_idx[tid])) {
                    s_val[tid] = v2; s_idx[tid] = i2;
                }
            }
            __syncthreads();
        }
        const float sj = s_val[0];
        const int   j  = s_idx[0];
        if (!(sj > -INFINITY)) { nsel = it; break; }
        if (tid == 0) {
            float4 b = g_cb[j];
            s_selS[it] = sj; s_selB[it] = b;
            s_bj[0] = b.x; s_bj[1] = b.y; s_bj[2] = b.z; s_bj[3] = b.w;
            s_bj[4] = g_carea[j];
        }
        __syncthreads();
        const float bx1 = s_bj[0], by1 = s_bj[1], bx2 = s_bj[2], by2 = s_bj[3], ba = s_bj[4];
        for (int idx = tid; idx < ns; idx += T) {
            float v = g_cs[idx];
            if (v == -INFINITY) continue;
            float4 b = g_cb[idx];
            float xx1 = fmaxf(bx1, b.x), yy1 = fmaxf(by1, b.y);
            float xx2 = fminf(bx2, b.z), yy2 = fminf(by2, b.w);
            float inter = __fmul_rn(fmaxf(__fsub_rn(xx2, xx1), 0.f),
                                    fmaxf(__fsub_rn(yy2, yy1), 0.f));
            float denom = __fadd_rn(__fsub_rn(__fadd_rn(g_carea[idx], ba), inter), 1e-8f);
            float iou = __fdiv_rn(inter, denom);
            if (iou > 0.5f) g_cs[idx] = -INFINITY;
        }
        __syncthreads();
    }
    __syncthreads();

    for (int i = tid; i < MAXDET; i += T) {
        float  s = (i < nsel) ? s_selS[i] : 0.f;
        float4 b = (i < nsel) ? s_selB[i] : make_float4(0.f, 0.f, 0.f, 0.f);
        out[i] = s;
        out[MAXDET + i] = (s > 0.f) ? 0.f : -1.f;
        out[2 * MAXDET + 4 * i + 0] = b.x;
        out[2 * MAXDET + 4 * i + 1] = b.y;
        out[2 * MAXDET + 4 * i + 2] = b.z;
        out[2 * MAXDET + 4 * i + 3] = b.w;
    }
}

// ---------------- host launcher ----------------
extern "C" void kernel_launch(void* const* d_in, const int* in_sizes, int n_in,
                              void* d_out, int out_size)
{
    const float* feats[5] = {
        (const float*)d_in[1], (const float*)d_in[2], (const float*)d_in[3],
        (const float*)d_in[4], (const float*)d_in[5]
    };
    const float* cls_w  = (const float*)d_in[6];
    const float* cls_b  = (const float*)d_in[7];
    const float* cls_ow = (const float*)d_in[8];
    const float* cls_ob = (const float*)d_in[9];
    const float* reg_w  = (const float*)d_in[10];
    const float* reg_b  = (const float*)d_in[11];
    const float* reg_ow = (const float*)d_in[12];
    const float* reg_ob = (const float*)d_in[13];

    float *feat, *hA0, *hA1, *hB0, *hB1, *wc, *wr, *wo;
    cudaGetSymbolAddress((void**)&feat, g_feat);
    cudaGetSymbolAddress((void**)&hA0, g_hA0);
    cudaGetSymbolAddress((void**)&hA1, g_hA1);
    cudaGetSymbolAddress((void**)&hB0, g_hB0);
    cudaGetSymbolAddress((void**)&hB1, g_hB1);
    cudaGetSymbolAddress((void**)&wc, g_wc);
    cudaGetSymbolAddress((void**)&wr, g_wr);
    cudaGetSymbolAddress((void**)&wo, g_wo);

    // transpose weights to k-major (rs*256 + c)
    transpose_w<<<2093, 256>>>(cls_w, reg_w, cls_ow, reg_ow);

    // gather feature pyramid into one packed buffer
    const size_t foff[5] = {0, 1638400, 2048000, 2150400, 2176000};
    const size_t fsz[5]  = {1638400, 409600, 102400, 25600, 6400};
    for (int l = 0; l < 5; l++)
        cudaMemcpyAsync(feat + foff[l], feats[l], fsz[l] * sizeof(float),
                        cudaMemcpyDeviceToDevice);

    const size_t LW = (size_t)256 * KTOT;
    dim3 gh(69, 2, 2);   // hidden layers: both heads, all levels
    dim3 go(69, 1, 2);   // out convs

    conv_fused<0><<<gh, 256>>>(feat, feat, wc + 0 * LW, wr + 0 * LW,
                               cls_b + 0,   reg_b + 0,   hA0, hB0);
    conv_fused<0><<<gh, 256>>>(hA0,  hB0,  wc + 1 * LW, wr + 1 * LW,
                               cls_b + 256, reg_b + 256, hA1, hB1);
    conv_fused<0><<<gh, 256>>>(hA1,  hB1,  wc + 2 * LW, wr + 2 * LW,
                               cls_b + 512, reg_b + 512, hA0, hB0);
    conv_fused<0><<<gh, 256>>>(hA0,  hB0,  wc + 3 * LW, wr + 3 * LW,
                               cls_b + 768, reg_b + 768, hA1, hB1);
    conv_fused<1><<<go, 256>>>(hA1,  hB1,  wo, wo + 9 * KTOT,
                               cls_ob, reg_ob, nullptr, nullptr);

    nms_kernel<<<1, 1024>>>((float*)d_out);
}

// round 5
// speedup vs baseline: 1.1811x; 1.1811x over previous
#include <cuda_runtime.h>
#include <math.h>

#define KTOT  2304          // 9*256, k = (ky*3+kx)*256 + c  (chain order)
#define NANCH 76725
#define MAXDET 300

#define BK 16
#define BN 128
#define NT  144             // KTOT/BK
#define BUFSZ (8525*256)

#define HID_ELEM (2304*256)       // per-layer weight elems
#define HID_TOT  (8*HID_ELEM)
#define OUT_ELEM (2304*64)

// ---------------- scratch (device globals; no allocation) ----------------
__device__ __align__(16) float  g_feat[BUFSZ];
__device__ __align__(16) float  g_hA0[BUFSZ];
__device__ __align__(16) float  g_hA1[BUFSZ];
__device__ __align__(16) float  g_hB0[BUFSZ];
__device__ __align__(16) float  g_hB1[BUFSZ];
__device__ __align__(16) float  g_wc[4 * HID_ELEM];   // cls hidden, [layer][k][m=256]
__device__ __align__(16) float  g_wr[4 * HID_ELEM];   // reg hidden, [layer][k][m=256]
__device__ __align__(16) float  g_wo_c[OUT_ELEM];     // cls out, [k][m=64] zero-padded (M=9)
__device__ __align__(16) float  g_wo_r[OUT_ELEM];     // reg out, [k][m=64] zero-padded (M=36)
__device__ float  g_scores[NANCH];
__device__ float4 g_boxes[NANCH];
__device__ float  g_cs[NANCH];
__device__ float4 g_cb[NANCH];
__device__ float  g_carea[NANCH];

// per-level tables
__constant__ int c_H[5]   = {80, 40, 20, 10, 5};
__constant__ int c_Pb[5]  = {0, 1638400, 2048000, 2150400, 2176000};
__constant__ int c_str[5] = {8, 16, 32, 64, 128};
__constant__ int c_ao[5]  = {0, 57600, 72000, 75600, 76500};

// ---------------- weight transpose: OIHW (m, c*9+rs) -> [k][m], k = rs*256+c ----
__global__ void transpose_w(const float* __restrict__ cw, const float* __restrict__ rw,
                            const float* __restrict__ cow, const float* __restrict__ row_)
{
    const int gid = blockIdx.x * 256 + threadIdx.x;
    if (gid < HID_TOT) {
        const int sub = gid / HID_ELEM;            // head*4 + layer
        const int rem = gid - sub * HID_ELEM;
        const int k = rem >> 8, m = rem & 255;
        const int c = k & 255, rs = k >> 8;
        const int head = sub >> 2, layer = sub & 3;
        const float* src = (head ? rw : cw) + (size_t)layer * HID_ELEM + (size_t)m * KTOT + c * 9 + rs;
        float*       dst = (head ? g_wr : g_wc) + (size_t)layer * HID_ELEM + (size_t)k * 256 + m;
        *dst = *src;
    } else {
        const int r2 = gid - HID_TOT;
        if (r2 >= 2 * OUT_ELEM) return;
        const int head = r2 / OUT_ELEM;
        const int r3 = r2 - head * OUT_ELEM;
        const int k = r3 >> 6, m = r3 & 63;
        const int c = k & 255, rs = k >> 8;
        const int M = head ? 36 : 9;
        float v = 0.f;
        if (m < M) v = ((head ? row_ : cow) + (size_t)m * KTOT)[c * 9 + rs];
        (head ? g_wo_r : g_wo_c)[k * 64 + m] = v;
    }
}

// ---------------- fused implicit-GEMM conv, 3-stage cp.async pipeline ----------------
// Serial FMA chain per output (kt, kk ascending, single accumulator) — DO NOT REORDER.
template <int OUTMODE, int MI>
__global__ __launch_bounds__(256, 2)
void conv_fused(const float* __restrict__ inC, const float* __restrict__ inR,
                const float* __restrict__ Wc,  const float* __restrict__ Wr,
                const float* __restrict__ bc,  const float* __restrict__ br,
                float* outC, float* outR)
{
    constexpr int BMv = 16 * MI;
    constexpr int MST = OUTMODE ? 64 : 256;

    const int bx = blockIdx.x;
    int l, ts;
    if      (bx < 50) { l = 0; ts = 0;  }
    else if (bx < 63) { l = 1; ts = 50; }
    else if (bx < 67) { l = 2; ts = 63; }
    else if (bx < 68) { l = 3; ts = 67; }
    else              { l = 4; ts = 68; }
    const int H = c_H[l];
    const int P = H * H;
    const int base = c_Pb[l];
    const int n0 = (bx - ts) * BN;
    const int z  = blockIdx.z;

    const float* in   = (z ? inR : inC) + base;
    const float* Wt   =  z ? Wr : Wc;
    const float* bias =  z ? br : bc;
    const int    m0   = blockIdx.y * BMv;

    const int tid = threadIdx.x;
    const int tx = tid & 15, ty = tid >> 4;
    const int lane16 = tid & 15;
    const int kr     = tid >> 4;          // k-offset within chunk (both A and B loaders)
    const int mcolA  = lane16 * MI;       // A columns this thread copies

    __shared__ float As[3][BK][BMv];
    __shared__ float Bs[3][BK][BN];

    float acc[MI][8];
#pragma unroll
    for (int i = 0; i < MI; i++)
#pragma unroll
        for (int j = 0; j < 8; j++) acc[i][j] = 0.f;

    int py[8], px[8];
#pragma unroll
    for (int j = 0; j < 8; j++) {
        int p = n0 + lane16 + j * 16;
        if (p < P) { py[j] = p / H; px[j] = p - py[j] * H; }
        else       { py[j] = -100000; px[j] = -100000; }
    }

    auto issue_tile = [&](int ktp, int buf) {
        // A tile: direct copy, weights already [k][m]
        const float* srcA = Wt + (size_t)(ktp * BK + kr) * MST + m0 + mcolA;
        unsigned dA = (unsigned)__cvta_generic_to_shared(&As[buf][kr][mcolA]);
#pragma unroll
        for (int q = 0; q < MI / 4; q++)
            asm volatile("cp.async.cg.shared.global [%0],[%1],16;\n"
                         :: "r"(dA + q * 16), "l"(srcA + q * 4));
        // B tile: im2col, 4B zero-fill copies
        const int rs = ktp >> 4;
        const int c  = ((ktp & 15) << 4) + kr;
        const int dy = rs / 3 - 1, dx = rs - 3 * (rs / 3) - 1;
        const float* cptr = in + (size_t)c * P;
#pragma unroll
        for (int j = 0; j < 8; j++) {
            int iy = py[j] + dy, ix = px[j] + dx;
            bool ok = (iy >= 0) && (iy < H) && (ix >= 0) && (ix < H);
            const float* s = cptr + (ok ? (iy * H + ix) : 0);
            unsigned dB = (unsigned)__cvta_generic_to_shared(&Bs[buf][kr][lane16 + j * 16]);
            int zf = ok ? 4 : 0;
            asm volatile("cp.async.ca.shared.global [%0],[%1],4,%2;\n"
                         :: "r"(dB), "l"(s), "r"(zf));
        }
        asm volatile("cp.async.commit_group;\n");
    };

    issue_tile(0, 0);
    issue_tile(1, 1);

    int cur = 0;
    for (int kt = 0; kt < NT; kt++) {
        asm volatile("cp.async.wait_group 1;\n");
        __syncthreads();

#pragma unroll
        for (int kk = 0; kk < BK; kk++) {
            float a[MI], b[8];
#pragma unroll
            for (int q = 0; q < MI / 4; q++)
                *(float4*)&a[4 * q] = *(const float4*)&As[cur][kk][ty * MI + 4 * q];
            *(float4*)&b[0] = *(const float4*)&Bs[cur][kk][tx * 8];
            *(float4*)&b[4] = *(const float4*)&Bs[cur][kk][tx * 8 + 4];
#pragma unroll
            for (int i = 0; i < MI; i++)
#pragma unroll
                for (int j = 0; j < 8; j++)
                    acc[i][j] = __fmaf_rn(a[i], b[j], acc[i][j]);
        }

        if (kt + 2 < NT) {
            int ib = cur + 2; if (ib >= 3) ib -= 3;
            issue_tile(kt + 2, ib);
        } else {
            asm volatile("cp.async.commit_group;\n");
        }
        cur = (cur == 2) ? 0 : cur + 1;
    }

    // ---------------- epilogues (bit-identical to round 4) ----------------
    if (OUTMODE == 0) {
        float* out = (z ? outR : outC) + base;
#pragma unroll
        for (int i = 0; i < MI; i++) {
            const int m = m0 + ty * MI + i;
            const float bsum = bias[m];
#pragma unroll
            for (int j = 0; j < 8; j++) {
                int p = n0 + tx * 8 + j;
                if (p < P) out[(size_t)m * P + p] = fmaxf(__fadd_rn(acc[i][j], bsum), 0.f);
            }
        }
    } else if (z == 0) {  // cls out: sigmoid via double
        const int aoff = c_ao[l];
#pragma unroll
        for (int i = 0; i < MI; i++) {
            const int m = ty * MI + i;
            if (m < 9) {
                const float bsum = bias[m];
#pragma unroll
                for (int j = 0; j < 8; j++) {
                    int p = n0 + tx * 8 + j;
                    if (p < P) {
                        float logit = __fadd_rn(acc[i][j], bsum);
                        double s = 1.0 / (1.0 + exp(-(double)logit));
                        g_scores[aoff + p * 9 + m] = (float)s;
                    }
                }
            }
        }
    } else {  // reg out + anchor decode
        const int aoff = c_ao[l];
        const int stride = c_str[l];
#pragma unroll
        for (int i = 0; i < MI; i += 4) {
            const int m = ty * MI + i;
            if (m + 3 < 36) {
                const int a = m >> 2;
                const int ri = a / 3, si = a - 3 * ri;
                const double ratio = (ri == 0) ? 0.5 : ((ri == 1) ? 1.0 : 2.0);
                const double scl   = (si == 0) ? 1.0 : exp2((double)si / 3.0);
                const double bsz   = (double)(stride * 4) * scl;
                const double wA    = sqrt((bsz * bsz) / ratio);
                const double hA    = wA * ratio;
                const float b0v = bias[m + 0], b1v = bias[m + 1];
                const float b2v = bias[m + 2], b3v = bias[m + 3];
#pragma unroll
                for (int j = 0; j < 8; j++) {
                    int p = n0 + tx * 8 + j;
                    if (p < P) {
                        int yy = p / H;
                        int xx = p - yy * H;
                        double cxd = ((double)xx + 0.5) * (double)stride;
                        double cyd = ((double)yy + 0.5) * (double)stride;
                        float ax1 = (float)(cxd - 0.5 * wA);
                        float ay1 = (float)(cyd - 0.5 * hA);
                        float ax2 = (float)(cxd + 0.5 * wA);
                        float ay2 = (float)(cyd + 0.5 * hA);
                        float aw = __fsub_rn(ax2, ax1), ah = __fsub_rn(ay2, ay1);
                        float acx = __fadd_rn(ax1, 0.5f * aw);
                        float acy = __fadd_rn(ay1, 0.5f * ah);
                        float t0 = __fadd_rn(acc[i + 0][j], b0v);
                        float t1 = __fadd_rn(acc[i + 1][j], b1v);
                        float t2 = __fadd_rn(acc[i + 2][j], b2v);
                        float t3 = __fadd_rn(acc[i + 3][j], b3v);
                        float pcx = __fadd_rn(acx, __fmul_rn(__fmul_rn(t0, 0.1f), aw));
                        float pcy = __fadd_rn(acy, __fmul_rn(__fmul_rn(t1, 0.1f), ah));
                        float pw  = __fmul_rn((float)exp((double)__fmul_rn(t2, 0.2f)), aw);
                        float ph  = __fmul_rn((float)exp((double)__fmul_rn(t3, 0.2f)), ah);
                        float x1 = __fsub_rn(pcx, 0.5f * pw), y1 = __fsub_rn(pcy, 0.5f * ph);
                        float x2 = __fadd_rn(pcx, 0.5f * pw), y2 = __fadd_rn(pcy, 0.5f * ph);
                        x1 = fminf(fmaxf(x1, 0.f), 640.f);
                        y1 = fminf(fmaxf(y1, 0.f), 640.f);
                        x2 = fminf(fmaxf(x2, 0.f), 640.f);
                        y2 = fminf(fmaxf(y2, 0.f), 640.f);
                        g_boxes[aoff + p * 9 + a] = make_float4(x1, y1, x2, y2);
                    }
                }
            }
        }
    }
}

// ---------------- single-block NMS: fused suppress+argmax, shuffle reductions ----------------
__global__ __launch_bounds__(1024)
void nms_kernel(float* __restrict__ out)
{
    const int T = 1024;
    const int tid = threadIdx.x;
    const int lane = tid & 31, w = tid >> 5;

    __shared__ int    s_warpcnt[32];
    __shared__ int    s_woff[32];
    __shared__ int    s_base;
    __shared__ float  s_wv[32];
    __shared__ int    s_wi[32];
    __shared__ float  s_pv;
    __shared__ int    s_pi;
    __shared__ float  s_selS[MAXDET];
    __shared__ float4 s_selB[MAXDET];

    if (tid == 0) s_base = 0;
    __syncthreads();

    // deterministic ordered compaction of candidates (score > 0.05)
    for (int c0 = 0; c0 < NANCH; c0 += T) {
        const int i = c0 + tid;
        float s = -1.f;
        bool pred = false;
        if (i < NANCH) {
            s = g_scores[i];
            pred = (s > 0.05f);
        }
        unsigned mask = __ballot_sync(0xffffffffu, pred);
        const int pos = __popc(mask & ((1u << lane) - 1u));
        if (lane == 0) s_warpcnt[w] = __popc(mask);
        __syncthreads();
        if (tid == 0) {
            int acc = s_base;
            for (int ww = 0; ww < 32; ww++) { s_woff[ww] = acc; acc += s_warpcnt[ww]; }
            s_base = acc;
        }
        __syncthreads();
        if (pred) {
            const int o = s_woff[w] + pos;
            g_cs[o] = s;
            float4 b = g_boxes[i];
            g_cb[o] = b;
            g_carea[o] = __fmul_rn(__fsub_rn(b.z, b.x), __fsub_rn(b.w, b.y));
        }
        __syncthreads();
    }
    const int ns = s_base;

    // greedy NMS: fused (suppress by previous pick) + argmax, one pass per iter
    int nsel = MAXDET;
    float pbx1 = 0.f, pby1 = 0.f, pbx2 = 0.f, pby2 = 0.f, pba = 0.f;
    int have = 0;
    for (int it = 0; it < MAXDET; it++) {
        float bv = -INFINITY; int bi = 0x7fffffff;
        for (int idx = tid; idx < ns; idx += T) {
            float v = g_cs[idx];
            if (have && v != -INFINITY) {
                float4 b = g_cb[idx];
                float xx1 = fmaxf(pbx1, b.x), yy1 = fmaxf(pby1, b.y);
                float xx2 = fminf(pbx2, b.z), yy2 = fminf(pby2, b.w);
                float inter = __fmul_rn(fmaxf(__fsub_rn(xx2, xx1), 0.f),
                                        fmaxf(__fsub_rn(yy2, yy1), 0.f));
                float denom = __fadd_rn(__fsub_rn(__fadd_rn(g_carea[idx], pba), inter), 1e-8f);
                float iou = __fdiv_rn(inter, denom);
                if (iou > 0.5f) { v = -INFINITY; g_cs[idx] = v; }
            }
            if (v > bv || (v == bv && idx < bi)) { bv = v; bi = idx; }
        }
#pragma unroll
        for (int off = 16; off; off >>= 1) {
            float v2 = __shfl_down_sync(0xffffffffu, bv, off);
            int   i2 = __shfl_down_sync(0xffffffffu, bi, off);
            if (v2 > bv || (v2 == bv && i2 < bi)) { bv = v2; bi = i2; }
        }
        if (lane == 0) { s_wv[w] = bv; s_wi[w] = bi; }
        __syncthreads();
        if (w == 0) {
            bv = s_wv[lane]; bi = s_wi[lane];
#pragma unroll
            for (int off = 16; off; off >>= 1) {
                float v2 = __shfl_down_sync(0xffffffffu, bv, off);
                int   i2 = __shfl_down_sync(0xffffffffu, bi, off);
                if (v2 > bv || (v2 == bv && i2 < bi)) { bv = v2; bi = i2; }
            }
            if (lane == 0) {
                s_pv = bv; s_pi = bi;
                if (bv > -INFINITY) { s_selS[it] = bv; s_selB[it] = g_cb[bi]; }
            }
        }
        __syncthreads();
        const float sj = s_pv;
        const int   j  = s_pi;
        if (!(sj > -INFINITY)) { nsel = it; break; }
        float4 pb = g_cb[j];
        pbx1 = pb.x; pby1 = pb.y; pbx2 = pb.z; pby2 = pb.w;
        pba = g_carea[j];
        have = 1;
    }
    __syncthreads();

    for (int i = tid; i < MAXDET; i += T) {
        float  s = (i < nsel) ? s_selS[i] : 0.f;
        float4 b = (i < nsel) ? s_selB[i] : make_float4(0.f, 0.f, 0.f, 0.f);
        out[i] = s;
        out[MAXDET + i] = (s > 0.f) ? 0.f : -1.f;
        out[2 * MAXDET + 4 * i + 0] = b.x;
        out[2 * MAXDET + 4 * i + 1] = b.y;
        out[2 * MAXDET + 4 * i + 2] = b.z;
        out[2 * MAXDET + 4 * i + 3] = b.w;
    }
}

// ---------------- host launcher ----------------
extern "C" void kernel_launch(void* const* d_in, const int* in_sizes, int n_in,
                              void* d_out, int out_size)
{
    const float* feats[5] = {
        (const float*)d_in[1], (const float*)d_in[2], (const float*)d_in[3],
        (const float*)d_in[4], (const float*)d_in[5]
    };
    const float* cls_w  = (const float*)d_in[6];
    const float* cls_b  = (const float*)d_in[7];
    const float* cls_ow = (const float*)d_in[8];
    const float* cls_ob = (const float*)d_in[9];
    const float* reg_w  = (const float*)d_in[10];
    const float* reg_b  = (const float*)d_in[11];
    const float* reg_ow = (const float*)d_in[12];
    const float* reg_ob = (const float*)d_in[13];

    float *feat, *hA0, *hA1, *hB0, *hB1, *wc, *wr, *woc, *wor;
    cudaGetSymbolAddress((void**)&feat, g_feat);
    cudaGetSymbolAddress((void**)&hA0, g_hA0);
    cudaGetSymbolAddress((void**)&hA1, g_hA1);
    cudaGetSymbolAddress((void**)&hB0, g_hB0);
    cudaGetSymbolAddress((void**)&hB1, g_hB1);
    cudaGetSymbolAddress((void**)&wc, g_wc);
    cudaGetSymbolAddress((void**)&wr, g_wr);
    cudaGetSymbolAddress((void**)&woc, g_wo_c);
    cudaGetSymbolAddress((void**)&wor, g_wo_r);

    // transpose weights to [k][m] layout
    const int ttot = HID_TOT + 2 * OUT_ELEM;
    transpose_w<<<(ttot + 255) / 256, 256>>>(cls_w, reg_w, cls_ow, reg_ow);

    // gather feature pyramid into one packed buffer
    const size_t foff[5] = {0, 1638400, 2048000, 2150400, 2176000};
    const size_t fsz[5]  = {1638400, 409600, 102400, 25600, 6400};
    for (int l = 0; l < 5; l++)
        cudaMemcpyAsync(feat + foff[l], feats[l], fsz[l] * sizeof(float),
                        cudaMemcpyDeviceToDevice);

    const size_t LW = (size_t)HID_ELEM;
    dim3 gh(69, 2, 2);   // hidden: BM=128 (MI=8), 2 M-tiles, 2 heads
    dim3 go(69, 1, 2);   // out:    BM=64  (MI=4), 1 M-tile,  2 heads

    conv_fused<0, 8><<<gh, 256>>>(feat, feat, wc + 0 * LW, wr + 0 * LW,
                                  cls_b + 0,   reg_b + 0,   hA0, hB0);
    conv_fused<0, 8><<<gh, 256>>>(hA0,  hB0,  wc + 1 * LW, wr + 1 * LW,
                                  cls_b + 256, reg_b + 256, hA1, hB1);
    conv_fused<0, 8><<<gh, 256>>>(hA1,  hB1,  wc + 2 * LW, wr + 2 * LW,
                                  cls_b + 512, reg_b + 512, hA0, hB0);
    conv_fused<0, 8><<<gh, 256>>>(hA0,  hB0,  wc + 3 * LW, wr + 3 * LW,
                                  cls_b + 768, reg_b + 768, hA1, hB1);
    conv_fused<1, 4><<<go, 256>>>(hA1,  hB1,  woc, wor,
                                  cls_ob, reg_ob, nullptr, nullptr);

    nms_kernel<<<1, 1024>>>((float*)d_out);
}